// round 6
// baseline (speedup 1.0000x reference)
#include <cuda_runtime.h>
#include <math.h>

// Problem constants
#define Bc  2
#define Sc  2048
#define Ec  1024
#define Hc  16
#define Dc  64
#define FFc 4096

// ---------------------------------------------------------------------------
// Scratch (static device globals; allocation inside kernel_launch is banned)
// ---------------------------------------------------------------------------
__device__ float g_attn[(size_t)Bc * Sc * Ec];   // attention output (pre-Wo)
__device__ float g_x   [(size_t)Bc * Sc * Ec];   // LN1 output
__device__ float g_t   [(size_t)Bc * Sc * Ec];   // pre-LN buffer (reused)
__device__ float g_h   [(size_t)Bc * Sc * FFc];  // FFN hidden (64MB)
__device__ float g_part[Bc * 16 * Ec];           // column-mean partials
__device__ float g_xavg[Bc * Ec];
__device__ float g_gpart[8 * Bc * Ec];           // gate GEMV partials
__device__ float g_gate[Bc * Ec];

// ---------------------------------------------------------------------------
// Column mean of query over sequence axis: xavg[b][e] = mean_s q[b,s,e]
// ---------------------------------------------------------------------------
__global__ void colmean_part_kernel(const float* __restrict__ q, float* __restrict__ part)
{
    const int b = blockIdx.x;      // 0..Bc-1
    const int p = blockIdx.y;      // 0..15 (s-slice of 128 rows)
    const int tid = threadIdx.x;   // 256 threads, float4 each -> 1024 cols
    const float* base = q + (size_t)b * Sc * Ec + (size_t)p * 128 * Ec;
    float4 acc = make_float4(0.f, 0.f, 0.f, 0.f);
#pragma unroll 4
    for (int s = 0; s < 128; ++s) {
        float4 v = ((const float4*)(base + (size_t)s * Ec))[tid];
        acc.x += v.x; acc.y += v.y; acc.z += v.z; acc.w += v.w;
    }
    ((float4*)(part + (size_t)(b * 16 + p) * Ec))[tid] = acc;
}

__global__ void colmean_fin_kernel(const float* __restrict__ part, float* __restrict__ xavg)
{
    const int b = blockIdx.x;
    const int tid = threadIdx.x;
    float4 acc = make_float4(0.f, 0.f, 0.f, 0.f);
#pragma unroll
    for (int p = 0; p < 16; ++p) {
        float4 v = ((const float4*)(part + (size_t)(b * 16 + p) * Ec))[tid];
        acc.x += v.x; acc.y += v.y; acc.z += v.z; acc.w += v.w;
    }
    const float inv = 1.0f / (float)Sc;
    ((float4*)(xavg + (size_t)b * Ec))[tid] =
        make_float4(acc.x * inv, acc.y * inv, acc.z * inv, acc.w * inv);
}

// ---------------------------------------------------------------------------
// Gate: sigmoid(xavg @ Wg + bg)   (split-K GEMV)
// ---------------------------------------------------------------------------
__global__ void gate_part_kernel(const float* __restrict__ xavg, const float* __restrict__ Wg,
                                 float* __restrict__ gp)
{
    const int idx = blockIdx.x * 256 + threadIdx.x;   // 0..Bc*Ec-1
    const int b = idx >> 10;
    const int e = idx & (Ec - 1);
    const int k0 = blockIdx.y * 128;
    const float* xa = xavg + (size_t)b * Ec;
    float acc = 0.f;
#pragma unroll 8
    for (int k = 0; k < 128; ++k)
        acc = fmaf(xa[k0 + k], Wg[(size_t)(k0 + k) * Ec + e], acc);
    gp[(size_t)blockIdx.y * (Bc * Ec) + idx] = acc;
}

__global__ void gate_fin_kernel(const float* __restrict__ gp, const float* __restrict__ bg,
                                float* __restrict__ gate)
{
    const int idx = blockIdx.x * 256 + threadIdx.x;
    const int e = idx & (Ec - 1);
    float acc = bg[e];
#pragma unroll
    for (int ky = 0; ky < 8; ++ky) acc += gp[(size_t)ky * (Bc * Ec) + idx];
    gate[idx] = 1.0f / (1.0f + expf(-acc));
}

// ---------------------------------------------------------------------------
// Causal flash attention (fp32). Block = 256 thr, 64x64 Q/K tiles, D=64.
// Heads are contiguous 64-wide slices of E. Scale applied after mask
// (equivalent: masked entries -> p = 0).
// ---------------------------------------------------------------------------
#define FAP 68   // smem pitch (floats)

__global__ __launch_bounds__(256)
void flash_attn_kernel(const float* __restrict__ Q, const float* __restrict__ K,
                       const float* __restrict__ V, float* __restrict__ O)
{
    extern __shared__ float sm[];
    float* Qs = sm;                  // [64][FAP] transposed: Qs[d][i]
    float* Ks = sm + 64 * FAP;       // transposed: Ks[d][j]
    float* Vs = sm + 2 * 64 * FAP;   // natural:    Vs[j][n]
    float* Ps = sm + 3 * 64 * FAP;   // natural:    Ps[i][j]

    const int qt = blockIdx.x;           // q tile (0..31)
    const int bh = blockIdx.y;           // b*H + h (0..31)
    const int b = bh >> 4, h = bh & 15;
    const int tid = threadIdx.x;
    const int ty = tid >> 4, tx = tid & 15;
    const size_t headoff = (size_t)b * Sc * Ec + (size_t)h * Dc;

    // Load Q tile, transposed into smem
    {
        const float* Qp = Q + headoff + (size_t)(qt * 64) * Ec;
        for (int t = tid; t < 1024; t += 256) {
            int r = t >> 4, c = (t & 15) * 4;
            float4 v = *(const float4*)(Qp + (size_t)r * Ec + c);
            Qs[(c + 0) * FAP + r] = v.x;
            Qs[(c + 1) * FAP + r] = v.y;
            Qs[(c + 2) * FAP + r] = v.z;
            Qs[(c + 3) * FAP + r] = v.w;
        }
    }

    float o[4][4];
    float mrow[4], lrow[4];
#pragma unroll
    for (int i = 0; i < 4; ++i) {
        mrow[i] = -1e30f; lrow[i] = 0.f;
#pragma unroll
        for (int j = 0; j < 4; ++j) o[i][j] = 0.f;
    }
    __syncthreads();

    for (int kt = 0; kt <= qt; ++kt) {
        __syncthreads();  // prev iteration's PV done reading Ks/Vs/Ps
        {
            const float* Kp = K + headoff + (size_t)(kt * 64) * Ec;
            const float* Vp = V + headoff + (size_t)(kt * 64) * Ec;
            for (int t = tid; t < 1024; t += 256) {
                int r = t >> 4, c = (t & 15) * 4;
                float4 kv = *(const float4*)(Kp + (size_t)r * Ec + c);
                Ks[(c + 0) * FAP + r] = kv.x;
                Ks[(c + 1) * FAP + r] = kv.y;
                Ks[(c + 2) * FAP + r] = kv.z;
                Ks[(c + 3) * FAP + r] = kv.w;
                float4 vv = *(const float4*)(Vp + (size_t)r * Ec + c);
                *(float4*)&Vs[r * FAP + c] = vv;
            }
        }
        __syncthreads();

        // S = Q K^T  (64x64, 4x4 per thread)
        float sc[4][4];
#pragma unroll
        for (int i = 0; i < 4; ++i)
#pragma unroll
            for (int j = 0; j < 4; ++j) sc[i][j] = 0.f;

#pragma unroll
        for (int d = 0; d < 64; ++d) {
            float4 aq = *(const float4*)&Qs[d * FAP + ty * 4];
            float4 bk = *(const float4*)&Ks[d * FAP + tx * 4];
            float a[4] = {aq.x, aq.y, aq.z, aq.w};
            float bb[4] = {bk.x, bk.y, bk.z, bk.w};
#pragma unroll
            for (int i = 0; i < 4; ++i)
#pragma unroll
                for (int j = 0; j < 4; ++j)
                    sc[i][j] = fmaf(a[i], bb[j], sc[i][j]);
        }

        const bool diag = (kt == qt);
#pragma unroll
        for (int i = 0; i < 4; ++i) {
#pragma unroll
            for (int j = 0; j < 4; ++j) {
                float v = sc[i][j] * 0.125f;                  // 1/sqrt(64)
                if (diag && (tx * 4 + j > ty * 4 + i)) v = -1e30f;
                sc[i][j] = v;
            }
            // row max across the 16-lane group owning this row
            float mx = fmaxf(fmaxf(sc[i][0], sc[i][1]), fmaxf(sc[i][2], sc[i][3]));
#pragma unroll
            for (int ofs = 8; ofs > 0; ofs >>= 1)
                mx = fmaxf(mx, __shfl_xor_sync(0xffffffffu, mx, ofs));
            float mn = fmaxf(mrow[i], mx);
            float corr = __expf(mrow[i] - mn);
            float rs = 0.f;
#pragma unroll
            for (int j = 0; j < 4; ++j) {
                float p = __expf(sc[i][j] - mn);
                sc[i][j] = p; rs += p;
            }
#pragma unroll
            for (int ofs = 8; ofs > 0; ofs >>= 1)
                rs += __shfl_xor_sync(0xffffffffu, rs, ofs);
            lrow[i] = lrow[i] * corr + rs;
            mrow[i] = mn;
#pragma unroll
            for (int j = 0; j < 4; ++j) o[i][j] *= corr;
        }

        // Write P to smem
#pragma unroll
        for (int i = 0; i < 4; ++i)
            *(float4*)&Ps[(ty * 4 + i) * FAP + tx * 4] =
                make_float4(sc[i][0], sc[i][1], sc[i][2], sc[i][3]);
        __syncthreads();

        // O += P @ V
#pragma unroll 8
        for (int j = 0; j < 64; ++j) {
            float av[4];
#pragma unroll
            for (int i = 0; i < 4; ++i) av[i] = Ps[(ty * 4 + i) * FAP + j];
            float4 bv = *(const float4*)&Vs[j * FAP + tx * 4];
            float bb[4] = {bv.x, bv.y, bv.z, bv.w};
#pragma unroll
            for (int i = 0; i < 4; ++i)
#pragma unroll
                for (int jj = 0; jj < 4; ++jj)
                    o[i][jj] = fmaf(av[i], bb[jj], o[i][jj]);
        }
    }

    // Normalize and store
    float* Op = O + headoff + (size_t)(qt * 64) * Ec;
#pragma unroll
    for (int i = 0; i < 4; ++i) {
        float inv = 1.0f / lrow[i];
        *(float4*)(Op + (size_t)(ty * 4 + i) * Ec + tx * 4) =
            make_float4(o[i][0] * inv, o[i][1] * inv, o[i][2] * inv, o[i][3] * inv);
    }
}

// ---------------------------------------------------------------------------
// SGEMM 128x128, BK=8, 256 threads, 8x8/thread, double-buffered smem.
// Row-major A(MxK) @ B(KxN) -> C(MxN). M,N,K multiples of 128/128/8.
// EPI 0: C = gate[b][n]*(acc + bias[n]) + aux2[m*N+n]   (Wo + gate + residual)
// EPI 1: C = gelu_exact(acc + bias[n])
// EPI 2: C = acc + bias[n] + aux1[m*N+n]                (W2 + residual)
// ---------------------------------------------------------------------------
template <int EPI>
__global__ __launch_bounds__(256)
void sgemm128(const float* __restrict__ A, const float* __restrict__ B,
              float* __restrict__ C, int M, int N, int K,
              const float* __restrict__ bias,
              const float* __restrict__ aux1, const float* __restrict__ aux2)
{
    __shared__ float As[2][8][128];  // transposed: As[k][m]
    __shared__ float Bs[2][8][128];  // natural:    Bs[k][n]

    const int tid = threadIdx.x;
    const int ty = tid >> 4, tx = tid & 15;
    const int bm = blockIdx.y * 128, bn = blockIdx.x * 128;

    const int ar = tid >> 1,  ak = (tid & 1) * 4;   // A loader: 128 rows x 8 cols
    const int br = tid >> 5,  bc = (tid & 31) * 4;  // B loader: 8 rows x 128 cols

    const float* Aptr = A + (size_t)(bm + ar) * K + ak;
    const float* Bptr = B + (size_t)br * N + bn + bc;

    // preload tile 0
    {
        float4 av = *(const float4*)Aptr;
        float4 bv = *(const float4*)Bptr;
        As[0][ak + 0][ar] = av.x;
        As[0][ak + 1][ar] = av.y;
        As[0][ak + 2][ar] = av.z;
        As[0][ak + 3][ar] = av.w;
        *(float4*)&Bs[0][br][bc] = bv;
    }
    __syncthreads();

    float acc[8][8];
#pragma unroll
    for (int i = 0; i < 8; ++i)
#pragma unroll
        for (int j = 0; j < 8; ++j) acc[i][j] = 0.f;

    const int nt = K >> 3;
    int cur = 0;
    for (int t = 0; t < nt; ++t) {
        float4 an, bnv;
        const bool more = (t + 1 < nt);
        if (more) {
            an  = *(const float4*)(Aptr + (size_t)(t + 1) * 8);
            bnv = *(const float4*)(Bptr + (size_t)(t + 1) * 8 * N);
        }
#pragma unroll
        for (int k = 0; k < 8; ++k) {
            float a[8], bb[8];
            *(float4*)&a[0] = *(const float4*)&As[cur][k][ty * 4];
            *(float4*)&a[4] = *(const float4*)&As[cur][k][64 + ty * 4];
            *(float4*)&bb[0] = *(const float4*)&Bs[cur][k][tx * 4];
            *(float4*)&bb[4] = *(const float4*)&Bs[cur][k][64 + tx * 4];
#pragma unroll
            for (int i = 0; i < 8; ++i)
#pragma unroll
                for (int j = 0; j < 8; ++j)
                    acc[i][j] = fmaf(a[i], bb[j], acc[i][j]);
        }
        if (more) {
            const int nx = cur ^ 1;
            As[nx][ak + 0][ar] = an.x;
            As[nx][ak + 1][ar] = an.y;
            As[nx][ak + 2][ar] = an.z;
            As[nx][ak + 3][ar] = an.w;
            *(float4*)&Bs[nx][br][bc] = bnv;
        }
        __syncthreads();
        cur ^= 1;
    }

    // Epilogue
#pragma unroll
    for (int i = 0; i < 8; ++i) {
        const int gr = bm + ((i < 4) ? (ty * 4 + i) : (60 + ty * 4 + i));
#pragma unroll
        for (int jh = 0; jh < 2; ++jh) {
            const int gc = bn + jh * 64 + tx * 4;
            float outv[4];
#pragma unroll
            for (int j = 0; j < 4; ++j) {
                float v = acc[i][jh * 4 + j];
                const int c = gc + j;
                if (EPI == 0) {
                    float gt = aux1[((gr >> 11) << 10) + c];   // gate[b][c]
                    v = gt * (v + bias[c]) + aux2[(size_t)gr * N + c];
                } else if (EPI == 1) {
                    float x = v + bias[c];
                    v = 0.5f * x * (1.0f + erff(x * 0.70710678118654752f));
                } else {
                    v = v + bias[c] + aux1[(size_t)gr * N + c];
                }
                outv[j] = v;
            }
            *(float4*)(C + (size_t)gr * N + gc) =
                make_float4(outv[0], outv[1], outv[2], outv[3]);
        }
    }
}

// ---------------------------------------------------------------------------
// LayerNorm over last dim (1024), one row per block, 256 threads (float4 each)
// ---------------------------------------------------------------------------
__global__ void ln1024_kernel(const float* __restrict__ in, const float* __restrict__ g,
                              const float* __restrict__ be, float* __restrict__ out)
{
    __shared__ float red[16];
    const int row = blockIdx.x;
    const int tid = threadIdx.x;
    float4 v = ((const float4*)(in + (size_t)row * Ec))[tid];
    float s = v.x + v.y + v.z + v.w;
    float q = v.x * v.x + v.y * v.y + v.z * v.z + v.w * v.w;
#pragma unroll
    for (int ofs = 16; ofs > 0; ofs >>= 1) {
        s += __shfl_xor_sync(0xffffffffu, s, ofs);
        q += __shfl_xor_sync(0xffffffffu, q, ofs);
    }
    const int w = tid >> 5;
    if ((tid & 31) == 0) { red[w] = s; red[8 + w] = q; }
    __syncthreads();
    s = 0.f; q = 0.f;
#pragma unroll
    for (int i = 0; i < 8; ++i) { s += red[i]; q += red[8 + i]; }
    const float mu = s * (1.0f / 1024.0f);
    const float var = q * (1.0f / 1024.0f) - mu * mu;
    const float rs = rsqrtf(var + 1e-5f);
    float4 gg = ((const float4*)g)[tid];
    float4 bb = ((const float4*)be)[tid];
    float4 o;
    o.x = (v.x - mu) * rs * gg.x + bb.x;
    o.y = (v.y - mu) * rs * gg.y + bb.y;
    o.z = (v.z - mu) * rs * gg.z + bb.z;
    o.w = (v.w - mu) * rs * gg.w + bb.w;
    ((float4*)(out + (size_t)row * Ec))[tid] = o;
}

// ---------------------------------------------------------------------------
// kernel_launch
// ---------------------------------------------------------------------------
extern "C" void kernel_launch(void* const* d_in, const int* in_sizes, int n_in,
                              void* d_out, int out_size)
{
    (void)in_sizes; (void)n_in; (void)out_size;
    const float* Vv  = (const float*)d_in[0];
    const float* Kk  = (const float*)d_in[1];
    const float* Qq  = (const float*)d_in[2];
    // d_in[3] = mask (int32 causal tril) — structure known, not needed
    const float* Wo  = (const float*)d_in[4];
    const float* bo  = (const float*)d_in[5];
    const float* Wg  = (const float*)d_in[6];
    const float* bg  = (const float*)d_in[7];
    const float* g1  = (const float*)d_in[8];
    const float* b1  = (const float*)d_in[9];
    const float* g2  = (const float*)d_in[10];
    const float* b2  = (const float*)d_in[11];
    const float* W1  = (const float*)d_in[12];
    const float* bf1 = (const float*)d_in[13];
    const float* W2  = (const float*)d_in[14];
    const float* bf2 = (const float*)d_in[15];
    float* out = (float*)d_out;

    float *p_attn, *p_x, *p_t, *p_h, *p_part, *p_xavg, *p_gpart, *p_gate;
    cudaGetSymbolAddress((void**)&p_attn,  g_attn);
    cudaGetSymbolAddress((void**)&p_x,     g_x);
    cudaGetSymbolAddress((void**)&p_t,     g_t);
    cudaGetSymbolAddress((void**)&p_h,     g_h);
    cudaGetSymbolAddress((void**)&p_part,  g_part);
    cudaGetSymbolAddress((void**)&p_xavg,  g_xavg);
    cudaGetSymbolAddress((void**)&p_gpart, g_gpart);
    cudaGetSymbolAddress((void**)&p_gate,  g_gate);

    const int fa_smem = 4 * 64 * FAP * (int)sizeof(float);  // 69632 B
    cudaFuncSetAttribute(flash_attn_kernel,
                         cudaFuncAttributeMaxDynamicSharedMemorySize, fa_smem);

    // gate path (tiny, off critical compute path)
    colmean_part_kernel<<<dim3(Bc, 16), 256>>>(Qq, p_part);
    colmean_fin_kernel<<<Bc, 256>>>(p_part, p_xavg);
    gate_part_kernel<<<dim3(Bc * Ec / 256, 8), 256>>>(p_xavg, Wg, p_gpart);
    gate_fin_kernel<<<Bc * Ec / 256, 256>>>(p_gpart, bg, p_gate);

    // causal attention
    flash_attn_kernel<<<dim3(Sc / 64, Bc * Hc), 256, fa_smem>>>(Qq, Kk, Vv, p_attn);

    // fc_out + gate*(.)+query residual -> LN1
    sgemm128<0><<<dim3(Ec / 128, Bc * Sc / 128), 256>>>(
        p_attn, Wo, p_t, Bc * Sc, Ec, Ec, bo, p_gate, Qq);
    ln1024_kernel<<<Bc * Sc, 256>>>(p_t, g1, b1, p_x);

    // FFN
    sgemm128<1><<<dim3(FFc / 128, Bc * Sc / 128), 256>>>(
        p_x, W1, p_h, Bc * Sc, FFc, Ec, bf1, nullptr, nullptr);
    sgemm128<2><<<dim3(Ec / 128, Bc * Sc / 128), 256>>>(
        p_h, W2, p_t, Bc * Sc, Ec, FFc, bf2, p_x, nullptr);

    ln1024_kernel<<<Bc * Sc, 256>>>(p_t, g2, b2, out);
}